// round 13
// baseline (speedup 1.0000x reference)
#include <cuda_runtime.h>
#include <cuda_bf16.h>
#include <cstdint>

#define NB 64      // batch
#define NL 512     // sequence length
#define ND 300     // embed dim
#define ND4 75     // float4 lanes per row
#define NC 128     // channels
#define CH 8       // token chunks per batch
#define TPC 64     // tokens per work unit
#define WAYS 4
#define JPER 16    // tokens per way
#define ROW_BYTES (ND * 4)            // 1200 (16B-aligned)
#define TILE_BYTES (TPC * ROW_BYTES)  // 76800
#define UNITS 4                       // work units per block
#define GGRID 128                     // gather blocks (128*4 = 512 units)

// Scratch (__device__ globals per allocation rules)
__device__ float4 g_part4[NB * CH * 3 * ND4];  // partial g sums
__device__ float  g_h[NB * 384];               // h[b][384]

// Dyn smem layout (bytes)
#define SM_ROWS0 0                    // stage0: 76800
#define SM_ROWS1 76800                // stage1: 76800
#define SM_SRED  153600               // WAYS*3*80 f4 = 15360
#define SM_CTAB  168960               // 3*512 floats = 6144
#define SM_MBAR  175104               // 2 mbarriers = 16
#define GATHER_SMEM 175120

__device__ __forceinline__ uint32_t smem_u32(const void* p) {
    uint32_t a;
    asm("{ .reg .u64 t; cvta.to.shared.u64 t, %1; cvt.u32.u64 %0, t; }"
        : "=r"(a) : "l"(p));
    return a;
}

// ---------------------------------------------------------------------------
// Kernel 1: persistent double-buffered TMA gather.
// 128 blocks x 4 units; fetch unit u+1 while computing unit u.
// ---------------------------------------------------------------------------
__global__ __launch_bounds__(320) void gather_kernel(
    const int*   __restrict__ x,
    const float* __restrict__ embed_w,
    const float* __restrict__ fc3_w,
    const float* __restrict__ fc4_w,
    const float* __restrict__ fc5_w)
{
    extern __shared__ char smem[];
    float4* sred = (float4*)(smem + SM_SRED);   // [WAYS][3][80]
    float*  ctab = (float*)(smem + SM_CTAB);    // [3][512]
    const uint32_t rows_s = smem_u32(smem);     // stage base
    const uint32_t mbar0  = smem_u32(smem + SM_MBAR);

    const int tid = threadIdx.x;
    const int d4  = tid % 80;
    const int y   = tid / 80;
    const int u0  = blockIdx.x * UNITS;

    // Prologue: mbarrier init + full coefficient table (once per block)
    if (tid == 0) {
        asm volatile("mbarrier.init.shared.b64 [%0], 1;" :: "r"(mbar0) : "memory");
        asm volatile("mbarrier.init.shared.b64 [%0], 1;" :: "r"(mbar0 + 8) : "memory");
    }
    for (int i = tid; i < 3 * NL; i += 320) {
        const int kk = i >> 9;
        const int t  = i & 511;
        const float* wk = (kk == 0) ? fc3_w : (kk == 1) ? fc4_w : fc5_w;
        const int k = kk + 3;
        int lo = t - k + 1; if (lo < 0) lo = 0;
        int hi = t; const int lim = NL - k - 1; if (hi > lim) hi = lim;
        float s = 0.f;
        #pragma unroll 5
        for (int l = lo; l <= hi; l++) s += __ldg(&wk[l]);
        ctab[i] = s;
    }
    asm volatile("fence.proxy.async.shared::cta;" ::: "memory");
    __syncthreads();

    // Issue helper (threads 0..63: one bulk copy each; tid 0: expect_tx)
    auto issue_unit = [&](int u, int st) {
        if (tid < TPC) {
            const int bb = u >> 3, ck = u & 7;
            const int row = __ldg(&x[bb * NL + ck * TPC + tid]);
            asm volatile("fence.proxy.async.shared::cta;" ::: "memory");
            if (tid == 0) {
                asm volatile("mbarrier.arrive.expect_tx.shared.b64 _, [%0], %1;"
                             :: "r"(mbar0 + st * 8), "r"((uint32_t)TILE_BYTES)
                             : "memory");
            }
            const char* src = (const char*)embed_w + (size_t)row * ROW_BYTES;
            const uint32_t dst = rows_s + st * TILE_BYTES + tid * ROW_BYTES;
            asm volatile(
                "cp.async.bulk.shared::cta.global.mbarrier::complete_tx::bytes "
                "[%0], [%1], %2, [%3];"
                :: "r"(dst), "l"(src), "r"((uint32_t)ROW_BYTES),
                   "r"(mbar0 + st * 8)
                : "memory");
        }
    };

    issue_unit(u0, 0);

    int parity0 = 0, parity1 = 0;

    #pragma unroll 1
    for (int su = 0; su < UNITS; su++) {
        const int u  = u0 + su;
        const int st = su & 1;

        if (su + 1 < UNITS) issue_unit(u + 1, st ^ 1);

        // Wait current stage (acquire)
        {
            const uint32_t mb = mbar0 + st * 8;
            const uint32_t ph = st ? (uint32_t)parity1 : (uint32_t)parity0;
            uint32_t done;
            asm volatile(
                "{\n\t.reg .pred p;\n\t"
                "mbarrier.try_wait.parity.acquire.cta.shared::cta.b64 p, [%1], %2;\n\t"
                "selp.b32 %0, 1, 0, p;\n\t}"
                : "=r"(done) : "r"(mb), "r"(ph) : "memory");
            if (!done) {
                asm volatile(
                    "{\n\t.reg .pred P1;\n\t"
                    "WL_%=:\n\t"
                    "mbarrier.try_wait.parity.acquire.cta.shared::cta.b64 P1, [%0], %1, 0x989680;\n\t"
                    "@P1 bra.uni WD_%=;\n\t"
                    "bra.uni WL_%=;\n\t"
                    "WD_%=:\n\t}"
                    :: "r"(mb), "r"(ph) : "memory");
            }
            if (st) parity1 ^= 1; else parity0 ^= 1;
        }

        // Weighted sums from the current stage
        const int bb = u >> 3, ck = u & 7;
        float4 a0 = make_float4(0.f, 0.f, 0.f, 0.f);
        float4 a1 = a0, a2 = a0;

        if (d4 < ND4) {
            const float4* rows4 = (const float4*)(smem + st * TILE_BYTES);
            const float* c0t = ctab + 0 * NL + ck * TPC;
            const float* c1t = ctab + 1 * NL + ck * TPC;
            const float* c2t = ctab + 2 * NL + ck * TPC;
            #pragma unroll 4
            for (int j = 0; j < JPER; j++) {
                const int jj = y * JPER + j;
                const float4 v = rows4[jj * ND4 + d4];
                const float c0 = c0t[jj], c1 = c1t[jj], c2 = c2t[jj];
                a0.x = fmaf(c0, v.x, a0.x); a0.y = fmaf(c0, v.y, a0.y);
                a0.z = fmaf(c0, v.z, a0.z); a0.w = fmaf(c0, v.w, a0.w);
                a1.x = fmaf(c1, v.x, a1.x); a1.y = fmaf(c1, v.y, a1.y);
                a1.z = fmaf(c1, v.z, a1.z); a1.w = fmaf(c1, v.w, a1.w);
                a2.x = fmaf(c2, v.x, a2.x); a2.y = fmaf(c2, v.y, a2.y);
                a2.z = fmaf(c2, v.z, a2.z); a2.w = fmaf(c2, v.w, a2.w);
            }
        }
        sred[(y * 3 + 0) * 80 + d4] = a0;
        sred[(y * 3 + 1) * 80 + d4] = a1;
        sred[(y * 3 + 2) * 80 + d4] = a2;
        __syncthreads();

        if (tid < 240) {
            const int kk = tid / 80;
            const int dd = tid % 80;
            if (dd < ND4) {
                float4 s = sred[(0 * 3 + kk) * 80 + dd];
                #pragma unroll
                for (int w = 1; w < WAYS; w++) {
                    const float4 v = sred[(w * 3 + kk) * 80 + dd];
                    s.x += v.x; s.y += v.y; s.z += v.z; s.w += v.w;
                }
                g_part4[((bb * CH + ck) * 3 + kk) * ND4 + dd] = s;
            }
        }
        __syncthreads();   // sred + stage buffer safe to reuse
    }
}

// ---------------------------------------------------------------------------
// Kernel 2: sim. grid (4 ctiles, 64 batches) = 256 blocks, 128 threads.
// (unchanged from R10 best)
// ---------------------------------------------------------------------------
__global__ __launch_bounds__(128) void sim_kernel(
    const float* __restrict__ conv_w,
    const float* __restrict__ conv_b,
    const float* __restrict__ fc3_w,
    const float* __restrict__ fc3_b,
    const float* __restrict__ fc4_w,
    const float* __restrict__ fc4_b,
    const float* __restrict__ fc5_w,
    const float* __restrict__ fc5_b)
{
    __shared__ float4 cw_s[32 * ND4];
    __shared__ float4 sg[3 * ND4];
    __shared__ float  qp[4 * 96];
    __shared__ float  sSk[3];

    const int tid  = threadIdx.x;
    const int warp = tid >> 5;
    const int lane = tid & 31;
    const int ct   = blockIdx.x;
    const int b    = blockIdx.y;
    const int c0   = ct * 32;

    if (warp < 3) {
        const float* wks[3] = {fc3_w, fc4_w, fc5_w};
        const float* w = wks[warp];
        const int n = NL - (warp + 3);
        float s = 0.f;
        for (int l = lane; l < n; l += 32) s += w[l];
        #pragma unroll
        for (int off = 16; off > 0; off >>= 1)
            s += __shfl_xor_sync(0xFFFFFFFFu, s, off);
        if (lane == 0) sSk[warp] = s;
    }

    {
        const float4* cwg = (const float4*)conv_w;
        #pragma unroll 4
        for (int j = tid; j < 32 * ND4; j += 128)
            cw_s[j] = __ldg(&cwg[c0 * ND4 + j]);
    }
    #pragma unroll
    for (int i = tid; i < 225; i += 128) {
        const float4* p = &g_part4[b * (CH * 225) + i];
        float4 s = p[0];
        #pragma unroll
        for (int ch = 1; ch < CH; ch++) {
            const float4 v = p[ch * 225];
            s.x += v.x; s.y += v.y; s.z += v.z; s.w += v.w;
        }
        sg[i] = s;
    }
    __syncthreads();

    const int c = lane;
    const int q = warp;
    {
        const int i0 = q * 19;
        const int i1 = (q == 3) ? ND4 : (i0 + 19);
        float s0 = 0.f, s1 = 0.f, s2 = 0.f;
        #pragma unroll 4
        for (int i = i0; i < i1; i++) {
            const float4 w  = cw_s[c * ND4 + i];
            const float4 g0 = sg[i];
            const float4 g1 = sg[75 + i];
            const float4 g2 = sg[150 + i];
            s0 = fmaf(w.x, g0.x, s0); s0 = fmaf(w.y, g0.y, s0);
            s0 = fmaf(w.z, g0.z, s0); s0 = fmaf(w.w, g0.w, s0);
            s1 = fmaf(w.x, g1.x, s1); s1 = fmaf(w.y, g1.y, s1);
            s1 = fmaf(w.z, g1.z, s1); s1 = fmaf(w.w, g1.w, s1);
            s2 = fmaf(w.x, g2.x, s2); s2 = fmaf(w.y, g2.y, s2);
            s2 = fmaf(w.z, g2.z, s2); s2 = fmaf(w.w, g2.w, s2);
        }
        qp[q * 96 + 0 * 32 + c] = s0;
        qp[q * 96 + 1 * 32 + c] = s1;
        qp[q * 96 + 2 * 32 + c] = s2;
    }
    __syncthreads();

    if (tid < 96) {
        const int kk = tid / 32;
        const int cc = tid % 32;
        float h = qp[0 * 96 + kk * 32 + cc] + qp[1 * 96 + kk * 32 + cc]
                + qp[2 * 96 + kk * 32 + cc] + qp[3 * 96 + kk * 32 + cc];
        const float bk = (kk == 0) ? fc3_b[0] : (kk == 1) ? fc4_b[0] : fc5_b[0];
        h += conv_b[c0 + cc] * sSk[kk] + bk;
        g_h[b * 384 + kk * NC + c0 + cc] = h;
    }
}

// ---------------------------------------------------------------------------
// Kernel 3: fc. grid (4 cotiles, 64 batches) = 256 blocks, 128 threads.
// (unchanged from R10 best)
// ---------------------------------------------------------------------------
__global__ __launch_bounds__(128) void fc_kernel(
    const float* __restrict__ fc_w,
    const float* __restrict__ fc_b,
    float* __restrict__ out)
{
    __shared__ float4 fw_s[32 * 97];
    __shared__ float4 sh[96];
    __shared__ float  qp[128];

    const int tid = threadIdx.x;
    const int ct  = blockIdx.x;
    const int b   = blockIdx.y;
    const int c0  = ct * 32;

    {
        const float4* fwg = (const float4*)fc_w;
        #pragma unroll 4
        for (int j = tid; j < 32 * 96; j += 128) {
            const int r = j / 96, i = j % 96;
            fw_s[r * 97 + i] = __ldg(&fwg[c0 * 96 + j]);
        }
        if (tid < 96) sh[tid] = ((const float4*)g_h)[b * 96 + tid];
    }
    __syncthreads();

    const int co = tid & 31;
    const int q  = tid >> 5;
    {
        float o = 0.f;
        #pragma unroll 4
        for (int i = q * 24; i < q * 24 + 24; i++) {
            const float4 w = fw_s[co * 97 + i];
            const float4 h = sh[i];
            o = fmaf(w.x, h.x, o); o = fmaf(w.y, h.y, o);
            o = fmaf(w.z, h.z, o); o = fmaf(w.w, h.w, o);
        }
        qp[q * 32 + co] = o;
    }
    __syncthreads();

    if (tid < 32)
        out[b * NC + c0 + tid] = qp[tid] + qp[32 + tid] + qp[64 + tid]
                               + qp[96 + tid] + fc_b[c0 + tid];
}

// ---------------------------------------------------------------------------
extern "C" void kernel_launch(void* const* d_in, const int* in_sizes, int n_in,
                              void* d_out, int out_size) {
    const int*   x       = (const int*)  d_in[0];
    const float* embed_w = (const float*)d_in[1];
    const float* conv_w  = (const float*)d_in[2];
    const float* conv_b  = (const float*)d_in[3];
    const float* fc3_w   = (const float*)d_in[4];
    const float* fc3_b   = (const float*)d_in[5];
    const float* fc4_w   = (const float*)d_in[6];
    const float* fc4_b   = (const float*)d_in[7];
    const float* fc5_w   = (const float*)d_in[8];
    const float* fc5_b   = (const float*)d_in[9];
    const float* fc_w    = (const float*)d_in[10];
    const float* fc_b    = (const float*)d_in[11];
    float* out = (float*)d_out;

    static int smem_set = 0;
    if (!smem_set) {
        cudaFuncSetAttribute(gather_kernel,
                             cudaFuncAttributeMaxDynamicSharedMemorySize, GATHER_SMEM);
        smem_set = 1;
    }

    gather_kernel<<<GGRID, 320, GATHER_SMEM>>>(x, embed_w, fc3_w, fc4_w, fc5_w);
    sim_kernel<<<dim3(4, NB), 128>>>(conv_w, conv_b, fc3_w, fc3_b,
                                     fc4_w, fc4_b, fc5_w, fc5_b);
    fc_kernel<<<dim3(4, NB), 128>>>(fc_w, fc_b, out);
}

// round 14
// speedup vs baseline: 1.0028x; 1.0028x over previous
#include <cuda_runtime.h>
#include <cuda_bf16.h>
#include <cstdint>

#define NB 64      // batch
#define NL 512     // sequence length
#define ND 300     // embed dim
#define ND4 75     // float4 lanes per row
#define NC 128     // channels
#define CH 16      // token chunks per batch
#define TPC 32     // tokens per gather block
#define WAYS 4
#define JPER 8     // tokens per way
#define ROW_BYTES (ND * 4)            // 1200
#define TILE_F4 (TPC * ND4)           // 2400 float4 = 38400 B

// Scratch (__device__ globals per allocation rules)
__device__ float4 g_part4[NB * CH * 3 * ND4];  // partial g sums
__device__ float  g_h[NB * 384];               // h[b][384]

// Dyn smem layout (bytes)
#define SM_ROWS 0                     // 38400
#define SM_SRED 38400                 // WAYS*3*80 f4 = 15360
#define SM_SIDX 53760                 // 32 ints = 128
#define SM_SC   53888                 // 3*32 floats = 384
#define GATHER_SMEM 54272

__device__ __forceinline__ uint32_t smem_u32(const void* p) {
    uint32_t a;
    asm("{ .reg .u64 t; cvta.to.shared.u64 t, %1; cvt.u32.u64 %0, t; }"
        : "=r"(a) : "l"(p));
    return a;
}

// ---------------------------------------------------------------------------
// Kernel 1: cp.async embedding gather.
// grid = NB*CH = 1024 blocks, 320 threads, 4 blocks/SM (54 KB smem, ~40 regs).
// Tile loads go through LDGSTS (no register buffers); latency hidden by
// 4 resident blocks per SM overlapping wait with compute.
// ---------------------------------------------------------------------------
__global__ __launch_bounds__(320, 4) void gather_kernel(
    const int*   __restrict__ x,
    const float* __restrict__ embed_w,
    const float* __restrict__ fc3_w,
    const float* __restrict__ fc4_w,
    const float* __restrict__ fc5_w)
{
    extern __shared__ char smem[];
    float4* rows4 = (float4*)(smem + SM_ROWS);
    float4* sred  = (float4*)(smem + SM_SRED);   // [WAYS][3][80]
    int*    sidx  = (int*)(smem + SM_SIDX);
    float*  sc    = (float*)(smem + SM_SC);      // [3][32]
    const uint32_t rows_s = smem_u32(rows4);

    const int b     = blockIdx.x >> 4;
    const int chunk = blockIdx.x & 15;
    const int tid   = threadIdx.x;
    const int d4    = tid % 80;
    const int y     = tid / 80;

    // Prologue: coefs (96 threads, <=5 cached loads each) + indices (32 threads)
    if (tid < 96) {
        const int kk = tid >> 5;
        const int tt = tid & 31;
        const int t  = chunk * TPC + tt;
        const float* wk = (kk == 0) ? fc3_w : (kk == 1) ? fc4_w : fc5_w;
        const int k = kk + 3;
        int lo = t - k + 1; if (lo < 0) lo = 0;
        int hi = t; const int lim = NL - k - 1; if (hi > lim) hi = lim;
        float s = 0.f;
        #pragma unroll 5
        for (int l = lo; l <= hi; l++) s += __ldg(&wk[l]);
        sc[kk * TPC + tt] = s;
    } else if (tid < 128) {
        const int tt = tid - 96;
        sidx[tt] = __ldg(&x[b * NL + chunk * TPC + tt]);
    }
    __syncthreads();

    // Async tile copy: 2400 f4, 16 B per cp.async, coalesced across threads.
    {
        const char* embc = (const char*)embed_w;
        #pragma unroll 4
        for (int i = tid; i < TILE_F4; i += 320) {
            const int tok = i / ND4;
            const int dj  = i - tok * ND4;
            const char* src = embc + (size_t)sidx[tok] * ROW_BYTES + dj * 16;
            const uint32_t dst = rows_s + (uint32_t)i * 16u;
            asm volatile("cp.async.cg.shared.global [%0], [%1], 16;"
                         :: "r"(dst), "l"(src) : "memory");
        }
        asm volatile("cp.async.commit_group;" ::: "memory");
        asm volatile("cp.async.wait_group 0;" ::: "memory");
    }
    __syncthreads();

    // Weighted sums from smem tile
    float4 a0 = make_float4(0.f, 0.f, 0.f, 0.f);
    float4 a1 = a0, a2 = a0;

    if (d4 < ND4) {
        #pragma unroll
        for (int j = 0; j < JPER; j++) {
            const int jj = y * JPER + j;
            const float4 v = rows4[jj * ND4 + d4];
            const float c0 = sc[0 * TPC + jj];
            const float c1 = sc[1 * TPC + jj];
            const float c2 = sc[2 * TPC + jj];
            a0.x = fmaf(c0, v.x, a0.x); a0.y = fmaf(c0, v.y, a0.y);
            a0.z = fmaf(c0, v.z, a0.z); a0.w = fmaf(c0, v.w, a0.w);
            a1.x = fmaf(c1, v.x, a1.x); a1.y = fmaf(c1, v.y, a1.y);
            a1.z = fmaf(c1, v.z, a1.z); a1.w = fmaf(c1, v.w, a1.w);
            a2.x = fmaf(c2, v.x, a2.x); a2.y = fmaf(c2, v.y, a2.y);
            a2.z = fmaf(c2, v.z, a2.z); a2.w = fmaf(c2, v.w, a2.w);
        }
    }
    sred[(y * 3 + 0) * 80 + d4] = a0;
    sred[(y * 3 + 1) * 80 + d4] = a1;
    sred[(y * 3 + 2) * 80 + d4] = a2;
    __syncthreads();

    if (tid < 240) {
        const int kk = tid / 80;
        const int dd = tid % 80;
        if (dd < ND4) {
            float4 s = sred[(0 * 3 + kk) * 80 + dd];
            #pragma unroll
            for (int w = 1; w < WAYS; w++) {
                const float4 v = sred[(w * 3 + kk) * 80 + dd];
                s.x += v.x; s.y += v.y; s.z += v.z; s.w += v.w;
            }
            g_part4[((b * CH + chunk) * 3 + kk) * ND4 + dd] = s;
        }
    }
}

// ---------------------------------------------------------------------------
// Kernel 2: sim. grid (4 ctiles, 64 batches) = 256 blocks, 128 threads.
// (R10 best; CH now 16)
// ---------------------------------------------------------------------------
__global__ __launch_bounds__(128) void sim_kernel(
    const float* __restrict__ conv_w,
    const float* __restrict__ conv_b,
    const float* __restrict__ fc3_w,
    const float* __restrict__ fc3_b,
    const float* __restrict__ fc4_w,
    const float* __restrict__ fc4_b,
    const float* __restrict__ fc5_w,
    const float* __restrict__ fc5_b)
{
    __shared__ float4 cw_s[32 * ND4];
    __shared__ float4 sg[3 * ND4];
    __shared__ float  qp[4 * 96];
    __shared__ float  sSk[3];

    const int tid  = threadIdx.x;
    const int warp = tid >> 5;
    const int lane = tid & 31;
    const int ct   = blockIdx.x;
    const int b    = blockIdx.y;
    const int c0   = ct * 32;

    if (warp < 3) {
        const float* wks[3] = {fc3_w, fc4_w, fc5_w};
        const float* w = wks[warp];
        const int n = NL - (warp + 3);
        float s = 0.f;
        for (int l = lane; l < n; l += 32) s += w[l];
        #pragma unroll
        for (int off = 16; off > 0; off >>= 1)
            s += __shfl_xor_sync(0xFFFFFFFFu, s, off);
        if (lane == 0) sSk[warp] = s;
    }

    {
        const float4* cwg = (const float4*)conv_w;
        #pragma unroll 4
        for (int j = tid; j < 32 * ND4; j += 128)
            cw_s[j] = __ldg(&cwg[c0 * ND4 + j]);
    }
    #pragma unroll
    for (int i = tid; i < 225; i += 128) {
        const float4* p = &g_part4[b * (CH * 225) + i];
        float4 s = p[0];
        #pragma unroll
        for (int ch = 1; ch < CH; ch++) {
            const float4 v = p[ch * 225];
            s.x += v.x; s.y += v.y; s.z += v.z; s.w += v.w;
        }
        sg[i] = s;
    }
    __syncthreads();

    const int c = lane;
    const int q = warp;
    {
        const int i0 = q * 19;
        const int i1 = (q == 3) ? ND4 : (i0 + 19);
        float s0 = 0.f, s1 = 0.f, s2 = 0.f;
        #pragma unroll 4
        for (int i = i0; i < i1; i++) {
            const float4 w  = cw_s[c * ND4 + i];
            const float4 g0 = sg[i];
            const float4 g1 = sg[75 + i];
            const float4 g2 = sg[150 + i];
            s0 = fmaf(w.x, g0.x, s0); s0 = fmaf(w.y, g0.y, s0);
            s0 = fmaf(w.z, g0.z, s0); s0 = fmaf(w.w, g0.w, s0);
            s1 = fmaf(w.x, g1.x, s1); s1 = fmaf(w.y, g1.y, s1);
            s1 = fmaf(w.z, g1.z, s1); s1 = fmaf(w.w, g1.w, s1);
            s2 = fmaf(w.x, g2.x, s2); s2 = fmaf(w.y, g2.y, s2);
            s2 = fmaf(w.z, g2.z, s2); s2 = fmaf(w.w, g2.w, s2);
        }
        qp[q * 96 + 0 * 32 + c] = s0;
        qp[q * 96 + 1 * 32 + c] = s1;
        qp[q * 96 + 2 * 32 + c] = s2;
    }
    __syncthreads();

    if (tid < 96) {
        const int kk = tid / 32;
        const int cc = tid % 32;
        float h = qp[0 * 96 + kk * 32 + cc] + qp[1 * 96 + kk * 32 + cc]
                + qp[2 * 96 + kk * 32 + cc] + qp[3 * 96 + kk * 32 + cc];
        const float bk = (kk == 0) ? fc3_b[0] : (kk == 1) ? fc4_b[0] : fc5_b[0];
        h += conv_b[c0 + cc] * sSk[kk] + bk;
        g_h[b * 384 + kk * NC + c0 + cc] = h;
    }
}

// ---------------------------------------------------------------------------
// Kernel 3: fc. grid (4 cotiles, 64 batches) = 256 blocks, 128 threads.
// (R10 best, unchanged)
// ---------------------------------------------------------------------------
__global__ __launch_bounds__(128) void fc_kernel(
    const float* __restrict__ fc_w,
    const float* __restrict__ fc_b,
    float* __restrict__ out)
{
    __shared__ float4 fw_s[32 * 97];
    __shared__ float4 sh[96];
    __shared__ float  qp[128];

    const int tid = threadIdx.x;
    const int ct  = blockIdx.x;
    const int b   = blockIdx.y;
    const int c0  = ct * 32;

    {
        const float4* fwg = (const float4*)fc_w;
        #pragma unroll 4
        for (int j = tid; j < 32 * 96; j += 128) {
            const int r = j / 96, i = j % 96;
            fw_s[r * 97 + i] = __ldg(&fwg[c0 * 96 + j]);
        }
        if (tid < 96) sh[tid] = ((const float4*)g_h)[b * 96 + tid];
    }
    __syncthreads();

    const int co = tid & 31;
    const int q  = tid >> 5;
    {
        float o = 0.f;
        #pragma unroll 4
        for (int i = q * 24; i < q * 24 + 24; i++) {
            const float4 w = fw_s[co * 97 + i];
            const float4 h = sh[i];
            o = fmaf(w.x, h.x, o); o = fmaf(w.y, h.y, o);
            o = fmaf(w.z, h.z, o); o = fmaf(w.w, h.w, o);
        }
        qp[q * 32 + co] = o;
    }
    __syncthreads();

    if (tid < 32)
        out[b * NC + c0 + tid] = qp[tid] + qp[32 + tid] + qp[64 + tid]
                               + qp[96 + tid] + fc_b[c0 + tid];
}

// ---------------------------------------------------------------------------
extern "C" void kernel_launch(void* const* d_in, const int* in_sizes, int n_in,
                              void* d_out, int out_size) {
    const int*   x       = (const int*)  d_in[0];
    const float* embed_w = (const float*)d_in[1];
    const float* conv_w  = (const float*)d_in[2];
    const float* conv_b  = (const float*)d_in[3];
    const float* fc3_w   = (const float*)d_in[4];
    const float* fc3_b   = (const float*)d_in[5];
    const float* fc4_w   = (const float*)d_in[6];
    const float* fc4_b   = (const float*)d_in[7];
    const float* fc5_w   = (const float*)d_in[8];
    const float* fc5_b   = (const float*)d_in[9];
    const float* fc_w    = (const float*)d_in[10];
    const float* fc_b    = (const float*)d_in[11];
    float* out = (float*)d_out;

    static int smem_set = 0;
    if (!smem_set) {
        cudaFuncSetAttribute(gather_kernel,
                             cudaFuncAttributeMaxDynamicSharedMemorySize, GATHER_SMEM);
        smem_set = 1;
    }

    gather_kernel<<<NB * CH, 320, GATHER_SMEM>>>(x, embed_w, fc3_w, fc4_w, fc5_w);
    sim_kernel<<<dim3(4, NB), 128>>>(conv_w, conv_b, fc3_w, fc3_b,
                                     fc4_w, fc4_b, fc5_w, fc5_b);
    fc_kernel<<<dim3(4, NB), 128>>>(fc_w, fc_b, out);
}